// round 2
// baseline (speedup 1.0000x reference)
#include <cuda_runtime.h>
#include <mma.h>
#include <cstdint>

using namespace nvcuda;

#define NB  16     // batch
#define MQ  512    // number of queries (K in reference)
#define NKV 2048   // keys per batch (N in reference)
#define DIM 1024   // embedding dim

// Scratch: qW = (query @ W) / 32, fp32
__device__ float g_qW[MQ * DIM];
// Fallback attention buffer if the harness output only holds `out`
__device__ float g_att[(size_t)NB * MQ * NKV];

// ---------------------------------------------------------------------------
// Kernel 1: qW = query @ W * (1/32), fp32 tiled SGEMM, 64x64 tile, BK=16
// ---------------------------------------------------------------------------
__global__ void qw_kernel(const float* __restrict__ query, const float* __restrict__ W) {
    __shared__ float As[16][68];   // [k][m]
    __shared__ float Bs[16][68];   // [k][n]
    const int m0 = blockIdx.y * 64;
    const int n0 = blockIdx.x * 64;
    const int tid = threadIdx.x;          // 256 threads
    const int tx = tid & 15, ty = tid >> 4;

    float acc[4][4] = {};

    for (int k0 = 0; k0 < DIM; k0 += 16) {
        #pragma unroll
        for (int it = 0; it < 4; it++) {
            int e = it * 256 + tid;
            int m  = e >> 4, kk = e & 15;
            As[kk][m] = query[(size_t)(m0 + m) * DIM + k0 + kk];
            int kk2 = e >> 6, n = e & 63;
            Bs[kk2][n] = W[(size_t)(k0 + kk2) * DIM + n0 + n];
        }
        __syncthreads();
        #pragma unroll
        for (int kk = 0; kk < 16; kk++) {
            float4 a4 = *(const float4*)&As[kk][ty * 4];
            float4 b4 = *(const float4*)&Bs[kk][tx * 4];
            float a[4] = {a4.x, a4.y, a4.z, a4.w};
            float b[4] = {b4.x, b4.y, b4.z, b4.w};
            #pragma unroll
            for (int i = 0; i < 4; i++)
                #pragma unroll
                for (int j = 0; j < 4; j++)
                    acc[i][j] += a[i] * b[j];
        }
        __syncthreads();
    }
    #pragma unroll
    for (int i = 0; i < 4; i++)
        #pragma unroll
        for (int j = 0; j < 4; j++)
            g_qW[(size_t)(m0 + ty * 4 + i) * DIM + n0 + tx * 4 + j] = acc[i][j] * 0.03125f;
}

// ---------------------------------------------------------------------------
// Kernel 2: logits[b, m, n] = sum_d qW[m, d] * key[b, n, d]   (NT, tf32 wmma)
// block tile 64x64, BK=32, 4 warps (each 32x32 via 2x2 frags of 16x16x8)
// ---------------------------------------------------------------------------
__global__ void logits_kernel(const float* __restrict__ key, float* __restrict__ att) {
    __shared__ float As[64][36];   // qW  tile: [m][k]
    __shared__ float Bs[64][36];   // key tile: [n][k]
    const int b  = blockIdx.z;
    const int m0 = blockIdx.y * 64;
    const int n0 = blockIdx.x * 64;
    const int tid = threadIdx.x;   // 128 threads
    const int warp = tid >> 5;
    const int wm = warp >> 1, wn = warp & 1;

    wmma::fragment<wmma::accumulator, 16, 16, 8, float> c[2][2];
    #pragma unroll
    for (int i = 0; i < 2; i++)
        #pragma unroll
        for (int j = 0; j < 2; j++)
            wmma::fill_fragment(c[i][j], 0.0f);

    const float* keyb = key + (size_t)b * NKV * DIM;

    for (int k0 = 0; k0 < DIM; k0 += 32) {
        #pragma unroll
        for (int it = 0; it < 4; it++) {
            int row = it * 16 + (tid >> 3);
            int col = (tid & 7) * 4;
            float4 va = *(const float4*)(g_qW + (size_t)(m0 + row) * DIM + k0 + col);
            As[row][col + 0] = wmma::__float_to_tf32(va.x);
            As[row][col + 1] = wmma::__float_to_tf32(va.y);
            As[row][col + 2] = wmma::__float_to_tf32(va.z);
            As[row][col + 3] = wmma::__float_to_tf32(va.w);
            float4 vb = *(const float4*)(keyb + (size_t)(n0 + row) * DIM + k0 + col);
            Bs[row][col + 0] = wmma::__float_to_tf32(vb.x);
            Bs[row][col + 1] = wmma::__float_to_tf32(vb.y);
            Bs[row][col + 2] = wmma::__float_to_tf32(vb.z);
            Bs[row][col + 3] = wmma::__float_to_tf32(vb.w);
        }
        __syncthreads();
        #pragma unroll
        for (int kk = 0; kk < 4; kk++) {
            wmma::fragment<wmma::matrix_a, 16, 16, 8, wmma::precision::tf32, wmma::row_major> a[2];
            wmma::fragment<wmma::matrix_b, 16, 16, 8, wmma::precision::tf32, wmma::col_major> bf[2];
            #pragma unroll
            for (int i = 0; i < 2; i++)
                wmma::load_matrix_sync(a[i], &As[wm * 32 + i * 16][kk * 8], 36);
            #pragma unroll
            for (int j = 0; j < 2; j++)
                wmma::load_matrix_sync(bf[j], &Bs[wn * 32 + j * 16][kk * 8], 36);
            #pragma unroll
            for (int i = 0; i < 2; i++)
                #pragma unroll
                for (int j = 0; j < 2; j++)
                    wmma::mma_sync(c[i][j], a[i], bf[j], c[i][j]);
        }
        __syncthreads();
    }

    #pragma unroll
    for (int i = 0; i < 2; i++)
        #pragma unroll
        for (int j = 0; j < 2; j++) {
            float* p = att + ((size_t)b * MQ + m0 + wm * 32 + i * 16) * NKV
                           + n0 + wn * 32 + j * 16;
            wmma::store_matrix_sync(p, c[i][j], NKV, wmma::mem_row_major);
        }
}

// ---------------------------------------------------------------------------
// Kernel 3: in-place masked softmax over N per row. Masked entries -> 0.
// Mask is int32 (bool promoted by the harness).
// ---------------------------------------------------------------------------
__global__ void softmax_kernel(const int* __restrict__ mask, float* __restrict__ att) {
    const size_t row = blockIdx.x;               // NB*MQ rows
    float* p = att + row * NKV;
    const int* mk = mask + row * NKV;
    const int tid = threadIdx.x;                 // 256 threads
    __shared__ float redm[8];
    __shared__ float reds[8];

    float mx = -INFINITY;
    for (int i = tid; i < NKV; i += 256) {
        float v = p[i];
        if (mk[i] != 0) mx = fmaxf(mx, v);
    }
    #pragma unroll
    for (int o = 16; o > 0; o >>= 1) mx = fmaxf(mx, __shfl_xor_sync(0xffffffffu, mx, o));
    if ((tid & 31) == 0) redm[tid >> 5] = mx;
    __syncthreads();
    mx = redm[0];
    #pragma unroll
    for (int i = 1; i < 8; i++) mx = fmaxf(mx, redm[i]);

    float s = 0.0f;
    for (int i = tid; i < NKV; i += 256) {
        float e = (mk[i] != 0) ? __expf(p[i] - mx) : 0.0f;
        p[i] = e;
        s += e;
    }
    #pragma unroll
    for (int o = 16; o > 0; o >>= 1) s += __shfl_xor_sync(0xffffffffu, s, o);
    if ((tid & 31) == 0) reds[tid >> 5] = s;
    __syncthreads();
    float tot = reds[0];
    #pragma unroll
    for (int i = 1; i < 8; i++) tot += reds[i];
    const float inv = 1.0f / tot;

    for (int i = tid; i < NKV; i += 256) p[i] *= inv;
}

// ---------------------------------------------------------------------------
// Kernel 4: out[b, m, d] = sum_n att[b, m, n] * key[b, n, d]  (NN, tf32 wmma)
// ---------------------------------------------------------------------------
__global__ void outgemm_kernel(const float* __restrict__ att, const float* __restrict__ key,
                               float* __restrict__ out) {
    __shared__ float As[64][36];   // att tile: [m][kdim]
    __shared__ float Bs[32][68];   // key tile: [kdim][d]
    const int b  = blockIdx.z;
    const int m0 = blockIdx.y * 64;
    const int n0 = blockIdx.x * 64;     // over DIM
    const int tid = threadIdx.x;        // 128 threads
    const int warp = tid >> 5;
    const int wm = warp >> 1, wn = warp & 1;

    wmma::fragment<wmma::accumulator, 16, 16, 8, float> c[2][2];
    #pragma unroll
    for (int i = 0; i < 2; i++)
        #pragma unroll
        for (int j = 0; j < 2; j++)
            wmma::fill_fragment(c[i][j], 0.0f);

    const float* attb = att + (size_t)b * MQ * NKV;
    const float* keyb = key + (size_t)b * NKV * DIM;

    for (int k0 = 0; k0 < NKV; k0 += 32) {
        #pragma unroll
        for (int it = 0; it < 4; it++) {
            int row = it * 16 + (tid >> 3);
            int col = (tid & 7) * 4;
            float4 va = *(const float4*)(attb + (size_t)(m0 + row) * NKV + k0 + col);
            As[row][col + 0] = wmma::__float_to_tf32(va.x);
            As[row][col + 1] = wmma::__float_to_tf32(va.y);
            As[row][col + 2] = wmma::__float_to_tf32(va.z);
            As[row][col + 3] = wmma::__float_to_tf32(va.w);
        }
        #pragma unroll
        for (int it = 0; it < 4; it++) {
            int row = it * 8 + (tid >> 4);
            int col = (tid & 15) * 4;
            float4 vb = *(const float4*)(keyb + (size_t)(k0 + row) * DIM + n0 + col);
            Bs[row][col + 0] = wmma::__float_to_tf32(vb.x);
            Bs[row][col + 1] = wmma::__float_to_tf32(vb.y);
            Bs[row][col + 2] = wmma::__float_to_tf32(vb.z);
            Bs[row][col + 3] = wmma::__float_to_tf32(vb.w);
        }
        __syncthreads();
        #pragma unroll
        for (int kk = 0; kk < 4; kk++) {
            wmma::fragment<wmma::matrix_a, 16, 16, 8, wmma::precision::tf32, wmma::row_major> a[2];
            wmma::fragment<wmma::matrix_b, 16, 16, 8, wmma::precision::tf32, wmma::row_major> bf[2];
            #pragma unroll
            for (int i = 0; i < 2; i++)
                wmma::load_matrix_sync(a[i], &As[wm * 32 + i * 16][kk * 8], 36);
            #pragma unroll
            for (int j = 0; j < 2; j++)
                wmma::load_matrix_sync(bf[j], &Bs[kk * 8][wn * 32 + j * 16], 68);
            #pragma unroll
            for (int i = 0; i < 2; i++)
                #pragma unroll
                for (int j = 0; j < 2; j++)
                    wmma::mma_sync(c[i][j], a[i], bf[j], c[i][j]);
        }
        __syncthreads();
    }

    #pragma unroll
    for (int i = 0; i < 2; i++)
        #pragma unroll
        for (int j = 0; j < 2; j++) {
            float* p = out + ((size_t)b * MQ + m0 + wm * 32 + i * 16) * DIM
                           + n0 + wn * 32 + j * 16;
            wmma::store_matrix_sync(p, c[i][j], DIM, wmma::mem_row_major);
        }
}

// ---------------------------------------------------------------------------
extern "C" void kernel_launch(void* const* d_in, const int* in_sizes, int n_in,
                              void* d_out, int out_size) {
    const float* query = (const float*)d_in[0];
    const float* key   = (const float*)d_in[1];
    const float* W     = (const float*)d_in[2];
    const int*   mask  = (const int*)d_in[3];   // bool promoted to int32 by harness

    float* out = (float*)d_out;
    const long long need = (long long)NB * MQ * DIM + (long long)NB * MQ * NKV;
    float* att;
    if ((long long)out_size >= need) {
        att = out + (size_t)NB * MQ * DIM;   // output tuple: (out, att)
    } else {
        void* p = nullptr;
        cudaGetSymbolAddress(&p, g_att);
        att = (float*)p;
    }

    {   // qW = query @ W / 32
        dim3 g(DIM / 64, MQ / 64);
        qw_kernel<<<g, 256>>>(query, W);
    }
    {   // raw logits -> att region
        dim3 g(NKV / 64, MQ / 64, NB);
        logits_kernel<<<g, 128>>>(key, att);
    }
    {   // masked softmax in place
        softmax_kernel<<<NB * MQ, 256>>>(mask, att);
    }
    {   // out = att @ key
        dim3 g(DIM / 64, MQ / 64, NB);
        outgemm_kernel<<<g, 128>>>(att, key, out);
    }
}